// round 8
// baseline (speedup 1.0000x reference)
#include <cuda_runtime.h>

// out[i, j] = (2*x[i, j] + 3) / (i + 1), x is 8192x8192 fp32.
// HBM-bound streaming, ~7.3 TB/s effective (91% of spec).
// R8: block-size sweep continues down the measured slope
// (512T: 78.7us, 256T: 74.3us, 128T: 73.4us ncu). THREADS=64, UNROLL=4
// (256 vecs/CTA, grid 65536) — halves per-CTA L1tex load batch again.
// Flat launch, front-batched LDG.128, streaming hints, 32-bit indexing.

static constexpr int N_ROWS = 8192;
static constexpr int N_COLS = 8192;
static constexpr int N_VEC = (N_ROWS / 4) * N_COLS;     // 2^24 float4s (fits int)
static constexpr int THREADS = 64;
static constexpr int UNROLL = 4;
// 2^24 / (64*4) = 65536 blocks, exact — no tail.
static constexpr int BLOCKS = N_VEC / (THREADS * UNROLL);

__global__ void __launch_bounds__(THREADS)
affine_rowdiv_kernel(const float4* __restrict__ in, float4* __restrict__ out) {
    int base = blockIdx.x * (THREADS * UNROLL) + threadIdx.x;

    // Front-batch 4 independent LDG.128 per thread.
    float4 v[UNROLL];
#pragma unroll
    for (int k = 0; k < UNROLL; k++) {
        v[k] = __ldcs(&in[base + k * THREADS]);
    }

#pragma unroll
    for (int k = 0; k < UNROLL; k++) {
        int idx = base + k * THREADS;
        // 2048 float4s per row -> row = idx >> 11
        int row = idx >> 11;
        float inv = 1.0f / (float)(row + 1);
        float4 r;
        r.x = fmaf(2.0f, v[k].x, 3.0f) * inv;
        r.y = fmaf(2.0f, v[k].y, 3.0f) * inv;
        r.z = fmaf(2.0f, v[k].z, 3.0f) * inv;
        r.w = fmaf(2.0f, v[k].w, 3.0f) * inv;
        __stcs(&out[idx], r);
    }
}

extern "C" void kernel_launch(void* const* d_in, const int* in_sizes, int n_in,
                              void* d_out, int out_size) {
    const float4* in = (const float4*)d_in[0];
    float4* out = (float4*)d_out;
    affine_rowdiv_kernel<<<BLOCKS, THREADS>>>(in, out);
}

// round 9
// speedup vs baseline: 1.0016x; 1.0016x over previous
#include <cuda_runtime.h>

// out[i, j] = (2*x[i, j] + 3) / (i + 1), x is 8192x8192 fp32.
// FINAL: HBM-bound streaming at 7.31 TB/s effective (91.4% of 8TB/s spec).
// Block-size U-curve minimum at 512 vecs/CTA (512T:78.7 / 256T:74.3 /
// 128T:73.4 / 64T:75.4 us ncu). THREADS=128, UNROLL=4, flat 32768-CTA grid,
// front-batched LDG.128 (MLP=4), streaming cache hints, 32-bit indexing.
// Swept and rejected: persistent grid (+11us), 64-bit idx (neutral),
// occupancy 48-82% (no effect on DRAM ceiling).

static constexpr int N_ROWS = 8192;
static constexpr int N_COLS = 8192;
static constexpr int N_VEC = (N_ROWS / 4) * N_COLS;     // 2^24 float4s (fits int)
static constexpr int THREADS = 128;
static constexpr int UNROLL = 4;
// 2^24 / (128*4) = 32768 blocks, exact — no tail.
static constexpr int BLOCKS = N_VEC / (THREADS * UNROLL);

__global__ void __launch_bounds__(THREADS)
affine_rowdiv_kernel(const float4* __restrict__ in, float4* __restrict__ out) {
    int base = blockIdx.x * (THREADS * UNROLL) + threadIdx.x;

    // Front-batch 4 independent LDG.128 per thread.
    float4 v[UNROLL];
#pragma unroll
    for (int k = 0; k < UNROLL; k++) {
        v[k] = __ldcs(&in[base + k * THREADS]);
    }

#pragma unroll
    for (int k = 0; k < UNROLL; k++) {
        int idx = base + k * THREADS;
        // 2048 float4s per row -> row = idx >> 11
        int row = idx >> 11;
        float inv = 1.0f / (float)(row + 1);
        float4 r;
        r.x = fmaf(2.0f, v[k].x, 3.0f) * inv;
        r.y = fmaf(2.0f, v[k].y, 3.0f) * inv;
        r.z = fmaf(2.0f, v[k].z, 3.0f) * inv;
        r.w = fmaf(2.0f, v[k].w, 3.0f) * inv;
        __stcs(&out[idx], r);
    }
}

extern "C" void kernel_launch(void* const* d_in, const int* in_sizes, int n_in,
                              void* d_out, int out_size) {
    const float4* in = (const float4*)d_in[0];
    float4* out = (float4*)d_out;
    affine_rowdiv_kernel<<<BLOCKS, THREADS>>>(in, out);
}